// round 7
// baseline (speedup 1.0000x reference)
#include <cuda_runtime.h>
#include <cuda_bf16.h>

// Shapes (fixed): char_feats [L=512, B=256, D=256] f32 (time-major),
// word_ids/attention_mask [B, L] i32, out = [W=128,B,D] f32 ++ [W,B] f32
#define Lc 512
#define Bc 256
#define Dc 256
#define Wc 128
#define CH 32                 // l-rows per chunk
#define NCH (Lc / CH)         // 16 chunks
#define NB 4                  // batch rows per block
#define NBG (Bc / NB)         // 64 b-groups
#define THREADS 256

// ---------------------------------------------------------------------------
// Fully fused: each block recomputes word structure for its NB batch rows
// from shared memory, streams its l-chunk's owned words, and handles a
// stripe of empty/invalid word slots + masks. No global scratch, no atomics.
// grid = (NCH, NBG), block = 256 = NB subs x 64 float4 lanes.
// ---------------------------------------------------------------------------
__global__ __launch_bounds__(THREADS) void fused_pool_kernel(
    const float4* __restrict__ cf,      // [L, B, D/4]
    const int* __restrict__ word_ids,   // [B, L]
    const int* __restrict__ attn,       // [B, L]
    float4* __restrict__ out,           // [W, B, D/4]
    float* __restrict__ mask_out)       // [W, B]
{
    const int t    = threadIdx.x;
    const int c    = blockIdx.x;        // l-chunk
    const int bg   = blockIdx.y;        // b-group
    const int sub  = t >> 6;            // 0..NB-1
    const int lane = t & 63;            // float4 lane over D
    const int b    = bg * NB + sub;

    __shared__ int s_wid[NB][Lc];
    __shared__ int s_start[NB][Wc + 1];
    __shared__ int s_sum[NB];

    // ---- phase 0: init ----
    if (t < NB) s_sum[t] = 0;
    for (int i = t; i < NB * (Wc + 1); i += THREADS) (&s_start[0][0])[i] = Lc;
    __syncthreads();

    // ---- phase 1: load word_ids rows; sum attn per row ----
    for (int idx = t; idx < NB * Lc; idx += THREADS) {
        const int row = idx >> 9, l = idx & (Lc - 1);
        s_wid[row][l] = word_ids[(bg * NB + row) * Lc + l];
    }
    {
        int asum = 0;
        for (int l = lane; l < Lc; l += 64) asum += attn[b * Lc + l];
        #pragma unroll
        for (int o = 16; o > 0; o >>= 1) asum += __shfl_down_sync(0xffffffffu, asum, o);
        if ((t & 31) == 0) atomicAdd(&s_sum[sub], asum);
    }
    __syncthreads();

    // ---- phase 2: mark run starts (unique writer per (row, word)) ----
    for (int idx = t; idx < NB * Lc; idx += THREADS) {
        const int row = idx >> 9, l = idx & (Lc - 1);
        const int w = s_wid[row][l];
        if (l == 0 || s_wid[row][l - 1] != w) s_start[row][w] = l;
    }
    __syncthreads();

    const int cap = s_sum[sub] - 1;            // valid l in [1, cap)
    const int wn  = s_wid[sub][Lc - 1] + 1;    // word count (ids sorted)
    const int* wid = s_wid[sub];
    const int* wst = s_start[sub];

    const float4 zero = make_float4(0.f, 0.f, 0.f, 0.f);

    // ---- phase 3: stripe duty — masks for w = c (mod NCH); zero empty slots
    for (int w2 = c; w2 < Wc; w2 += NCH) {
        int lo = min(max(wst[w2], 1), cap);
        int hi = min(max(wst[w2 + 1], 1), cap);
        if (lane == 0) mask_out[w2 * Bc + b] = (w2 < wn) ? 1.0f : 0.0f;
        if (hi - lo <= 0)
            out[((size_t)w2 * Bc + b) * (Dc / 4) + lane] = zero;
    }

    // ---- phase 4: stream owned words of this chunk ----
    const int r0 = max(c * CH, 1);
    const int r1 = min(c * CH + CH, cap);
    if (r0 >= r1) return;

    int l0 = r0;
    if (r0 >= 2) while (l0 < r1 && wid[l0] == wid[l0 - 1]) ++l0;  // skip continuation
    if (l0 >= r1) return;

    const int wlast = wid[r1 - 1];
    const int E = min(wst[wlast + 1], cap);    // end of last owned word's run
    const int n = E - l0;

    const size_t stride = (size_t)Bc * (Dc / 4);
    const float4* p = cf + ((size_t)l0 * Bc + b) * (Dc / 4) + lane;

    // 8-deep prefetch ring
    float4 q0 = zero, q1 = zero, q2 = zero, q3 = zero;
    float4 q4 = zero, q5 = zero, q6 = zero, q7 = zero;
    if (0 < n) q0 = p[0 * stride];
    if (1 < n) q1 = p[1 * stride];
    if (2 < n) q2 = p[2 * stride];
    if (3 < n) q3 = p[3 * stride];
    if (4 < n) q4 = p[4 * stride];
    if (5 < n) q5 = p[5 * stride];
    if (6 < n) q6 = p[6 * stride];
    if (7 < n) q7 = p[7 * stride];
    int lpf = 8;

    float4 acc = zero;
    int i = 0;
    int w = wid[l0];

#define STEP(P)                                                              \
    {                                                                        \
        const float4 v = P;                                                  \
        if (lpf < n) P = p[(size_t)lpf * stride];                            \
        ++lpf;                                                               \
        acc.x += v.x; acc.y += v.y; acc.z += v.z; acc.w += v.w;              \
        const int gl = l0 + i;                                               \
        ++i;                                                                 \
        if (gl + 1 == E || wid[gl + 1] != w) {                               \
            const int lo  = max(wst[w], 1);                                  \
            const int hi  = min(wst[w + 1], cap);                            \
            const float inv = 1.0f / (float)(hi - lo);                       \
            float4 r;                                                        \
            r.x = acc.x * inv; r.y = acc.y * inv;                            \
            r.z = acc.z * inv; r.w = acc.w * inv;                            \
            out[((size_t)w * Bc + b) * (Dc / 4) + lane] = r;                 \
            acc = zero;                                                      \
            if (gl + 1 < E) w = wid[gl + 1];                                 \
        }                                                                    \
    }

    while (i < n) {
        STEP(q0); if (i >= n) break;
        STEP(q1); if (i >= n) break;
        STEP(q2); if (i >= n) break;
        STEP(q3); if (i >= n) break;
        STEP(q4); if (i >= n) break;
        STEP(q5); if (i >= n) break;
        STEP(q6); if (i >= n) break;
        STEP(q7);
    }
#undef STEP
}

// ---------------------------------------------------------------------------
extern "C" void kernel_launch(void* const* d_in, const int* in_sizes, int n_in,
                              void* d_out, int out_size) {
    const float* char_feats = (const float*)d_in[0];
    const int*   word_ids   = (const int*)d_in[1];
    const int*   attn       = (const int*)d_in[2];

    float* out_feats = (float*)d_out;
    float* out_mask  = out_feats + (size_t)Wc * Bc * Dc;

    fused_pool_kernel<<<dim3(NCH, NBG), THREADS>>>(
        (const float4*)char_feats, word_ids, attn,
        (float4*)out_feats, out_mask);
}

// round 10
// speedup vs baseline: 1.6244x; 1.6244x over previous
#include <cuda_runtime.h>
#include <cuda_bf16.h>

// Shapes (fixed): char_feats [L=512, B=256, D=256] f32 (time-major),
// word_ids/attention_mask [B, L] i32, out = [W=128,B,D] f32 ++ [W,B] f32
#define Lc 512
#define Bc 256
#define Dc 256
#define Wc 128
#define GW 8          // words per block

// ---------------------------------------------------------------------------
// Single fused kernel. grid = (Wc/GW=16, Bc), block = 64 threads (one float4
// lane over D each). Each block:
//   A) caches its word_ids row in smem (int4), sums attn row on the fly
//   B) binary-searches its 9 group boundaries in smem (ids sorted+densified)
//   C) writes masks for its GW words
//   D) streams the group's contiguous char run with a 4-deep prefetch ring
//      (identical to the proven R3 loop, rel_err 0.0)
// No global scratch, no atomics, one launch.
// ---------------------------------------------------------------------------
__global__ __launch_bounds__(64) void fused_kernel(
    const float4* __restrict__ cf,      // [L, B, D/4]
    const int*    __restrict__ word_ids,// [B, L]
    const int*    __restrict__ attn,    // [B, L]
    float4* __restrict__ out,           // [W, B, D/4]
    float*  __restrict__ mask_out)      // [W, B]
{
    const int lane = threadIdx.x;       // 0..63
    const int b    = blockIdx.y;
    const int w0   = blockIdx.x * GW;

    __shared__ int   s_ids[Lc];
    __shared__ int   sE[GW + 1];
    __shared__ int   s_red[2];

    // ---- A: cache word_ids row (int4), sum attn row ----
    {
        const int4* wrow = (const int4*)(word_ids + b * Lc);   // 128 int4
        const int4* arow = (const int4*)(attn + b * Lc);
        int4* sd = (int4*)s_ids;
        int asum = 0;
        #pragma unroll
        for (int k = 0; k < 2; ++k) {
            const int idx = lane + k * 64;
            sd[idx] = wrow[idx];
            const int4 a = arow[idx];
            asum += a.x + a.y + a.z + a.w;
        }
        #pragma unroll
        for (int o = 16; o > 0; o >>= 1) asum += __shfl_down_sync(0xffffffffu, asum, o);
        if ((lane & 31) == 0) s_red[lane >> 5] = asum;
    }
    __syncthreads();

    const int cap = (s_red[0] + s_red[1] - 2) + 1;   // valid l in [1, cap)
    const int wn  = s_ids[Lc - 1] + 1;

    // ---- B: binary search boundaries (lanes 0..GW) + clamp ----
    if (lane <= GW) {
        const int target = w0 + lane;
        int lo = 0, hi = Lc;
        while (lo < hi) {
            const int mid = (lo + hi) >> 1;
            if (s_ids[mid] < target) lo = mid + 1; else hi = mid;
        }
        // clamp to [1, cap) window like R3
        int s = lo;
        s = (s < 1) ? 1 : s;
        s = (s > cap) ? cap : s;
        sE[lane] = s;
    }

    // ---- C: masks ----
    if (lane < GW) mask_out[(w0 + lane) * Bc + b] = (w0 + lane < wn) ? 1.0f : 0.0f;
    __syncthreads();

    // ---- D: stream (R3-proven loop) ----
    const size_t stride = (size_t)Bc * (Dc / 4);
    const float4* cfb = cf + ((size_t)b * (Dc / 4) + lane);
    float4* ob = out + (((size_t)w0 * Bc + b) * (Dc / 4) + lane);
    const size_t wstep = (size_t)Bc * (Dc / 4);

    const float4 zero = make_float4(0.f, 0.f, 0.f, 0.f);

    int l    = sE[0];
    const int lend = sE[GW];
    int wi   = 0;
    int e_cur  = l;
    int e_next = sE[1];
    float4 acc = zero;

    // leading empty words (and fully-empty group)
    while (wi < GW && e_next == l) {
        ob[(size_t)wi * wstep] = zero;
        e_cur = e_next;
        ++wi;
        e_next = (wi < GW) ? sE[wi + 1] : 0x7fffffff;
    }

    // prime 4-deep prefetch ring
    float4 p0 = zero, p1 = zero, p2 = zero, p3 = zero;
    if (l + 0 < lend) p0 = cfb[(size_t)(l + 0) * stride];
    if (l + 1 < lend) p1 = cfb[(size_t)(l + 1) * stride];
    if (l + 2 < lend) p2 = cfb[(size_t)(l + 2) * stride];
    if (l + 3 < lend) p3 = cfb[(size_t)(l + 3) * stride];
    int l4 = l + 4;

#define STEP(P)                                                           \
    {                                                                     \
        const float4 v = P;                                               \
        if (l4 < lend) P = cfb[(size_t)l4 * stride];                      \
        ++l4;                                                             \
        acc.x += v.x; acc.y += v.y; acc.z += v.z; acc.w += v.w;           \
        ++l;                                                              \
        while (wi < GW && l == e_next) {                                  \
            const int cnt = e_next - e_cur;                               \
            const float inv = 1.0f / (float)(cnt > 0 ? cnt : 1);          \
            float4 r;                                                     \
            r.x = acc.x * inv; r.y = acc.y * inv;                         \
            r.z = acc.z * inv; r.w = acc.w * inv;                         \
            ob[(size_t)wi * wstep] = r;                                   \
            acc = zero;                                                   \
            e_cur = e_next;                                               \
            ++wi;                                                         \
            e_next = (wi < GW) ? sE[wi + 1] : 0x7fffffff;                 \
        }                                                                 \
    }

    while (l < lend) {
        STEP(p0); if (l >= lend) break;
        STEP(p1); if (l >= lend) break;
        STEP(p2); if (l >= lend) break;
        STEP(p3);
    }
#undef STEP
}

// ---------------------------------------------------------------------------
extern "C" void kernel_launch(void* const* d_in, const int* in_sizes, int n_in,
                              void* d_out, int out_size) {
    const float* char_feats = (const float*)d_in[0];
    const int*   word_ids   = (const int*)d_in[1];
    const int*   attn       = (const int*)d_in[2];

    float* out_feats = (float*)d_out;
    float* out_mask  = out_feats + (size_t)Wc * Bc * Dc;

    fused_kernel<<<dim3(Wc / GW, Bc), 64>>>(
        (const float4*)char_feats, word_ids, attn,
        (float4*)out_feats, out_mask);
}